// round 1
// baseline (speedup 1.0000x reference)
#include <cuda_runtime.h>
#include <math.h>

// Problem constants
#define Bc 4
#define Tc 2048
#define Ec 1024
#define Hc 16
#define HSc 64
#define BHc (Bc*Hc)

// Scratch (static device arrays; allocation APIs are forbidden)
__device__ float g_Q[(size_t)BHc*Tc*HSc];   // 32 MB
__device__ float g_K[(size_t)BHc*Tc*HSc];   // 32 MB
__device__ float g_V[(size_t)BHc*Tc*HSc];   // 32 MB
__device__ float g_O[(size_t)BHc*Tc*HSc];   // 32 MB
__device__ float g_S[(size_t)BHc*Tc*Tc];    // 1 GiB, lower-tri tiles only
__device__ float g_m[BHc*Tc];
__device__ float g_iz[BHc*Tc];

// ---------------------------------------------------------------------------
// Kernel 1: fused QKV projection.
// Per (bh, t-tile of 64): Q/K/V[64, 64] = X[64, E] @ W{q,k,v}[h][E, 64]
// ---------------------------------------------------------------------------
__global__ void qkv_kernel(const float* __restrict__ x,
                           const float* __restrict__ Wq,
                           const float* __restrict__ Wk,
                           const float* __restrict__ Wv) {
    __shared__ float Xs[64][33];
    __shared__ float Ws[3][32][64];
    const int ti = blockIdx.x, bh = blockIdx.y;
    const int b = bh >> 4, h = bh & 15;
    const int tid = threadIdx.x;
    const int tx = tid & 15, ty = tid >> 4;

    const float* xb = x + ((size_t)b*Tc + ti*64) * Ec;
    const float* wq = Wq + (size_t)h*Ec*HSc;
    const float* wk = Wk + (size_t)h*Ec*HSc;
    const float* wv = Wv + (size_t)h*Ec*HSc;

    float acc[3][4][4] = {};

    for (int e0 = 0; e0 < Ec; e0 += 32) {
        #pragma unroll
        for (int it = 0; it < 8; it++) {
            int idx = it*256 + tid;
            int r = idx >> 5, c = idx & 31;
            Xs[r][c] = xb[(size_t)r*Ec + e0 + c];
        }
        #pragma unroll
        for (int it = 0; it < 8; it++) {
            int idx = it*256 + tid;
            int r = idx >> 6, c = idx & 63;
            int off = (e0 + r)*HSc + c;
            Ws[0][r][c] = wq[off];
            Ws[1][r][c] = wk[off];
            Ws[2][r][c] = wv[off];
        }
        __syncthreads();
        #pragma unroll
        for (int kk = 0; kk < 32; kk++) {
            float a[4];
            #pragma unroll
            for (int i = 0; i < 4; i++) a[i] = Xs[ty*4+i][kk];
            #pragma unroll
            for (int j = 0; j < 4; j++) {
                float bq = Ws[0][kk][tx*4+j];
                float bk = Ws[1][kk][tx*4+j];
                float bv = Ws[2][kk][tx*4+j];
                #pragma unroll
                for (int i = 0; i < 4; i++) {
                    acc[0][i][j] = fmaf(a[i], bq, acc[0][i][j]);
                    acc[1][i][j] = fmaf(a[i], bk, acc[1][i][j]);
                    acc[2][i][j] = fmaf(a[i], bv, acc[2][i][j]);
                }
            }
        }
        __syncthreads();
    }

    const size_t base = (size_t)bh*Tc + (size_t)ti*64;
    #pragma unroll
    for (int i = 0; i < 4; i++) {
        size_t o = (base + ty*4 + i) * HSc;
        #pragma unroll
        for (int j = 0; j < 4; j++) {
            int d = tx*4 + j;
            g_Q[o+d] = acc[0][i][j];
            g_K[o+d] = acc[1][i][j];
            g_V[o+d] = acc[2][i][j];
        }
    }
}

// ---------------------------------------------------------------------------
// Kernel 2: scores S[t][s] = Q[t]·K[s] / 32, lower-triangular tiles only.
// Masked entries (s > t, diagonal tiles) get -1e30.
// ---------------------------------------------------------------------------
__global__ void scores_kernel() {
    const int tj = blockIdx.x, ti = blockIdx.y, bh = blockIdx.z;
    if (tj > ti) return;
    __shared__ float Qs[64][65];
    __shared__ float Ks[64][65];
    const int tid = threadIdx.x;
    const int tx = tid & 15, ty = tid >> 4;

    const float* Qp = g_Q + ((size_t)bh*Tc + ti*64) * HSc;
    const float* Kp = g_K + ((size_t)bh*Tc + tj*64) * HSc;
    #pragma unroll
    for (int it = 0; it < 16; it++) {
        int idx = it*256 + tid;
        int r = idx >> 6, c = idx & 63;
        Qs[r][c] = Qp[r*HSc + c];
        Ks[r][c] = Kp[r*HSc + c];
    }
    __syncthreads();

    float acc[4][4] = {};
    #pragma unroll
    for (int kk = 0; kk < 64; kk++) {
        float a[4], bb[4];
        #pragma unroll
        for (int i = 0; i < 4; i++) a[i]  = Qs[ty*4+i][kk];
        #pragma unroll
        for (int j = 0; j < 4; j++) bb[j] = Ks[tx*4+j][kk];
        #pragma unroll
        for (int i = 0; i < 4; i++)
            #pragma unroll
            for (int j = 0; j < 4; j++)
                acc[i][j] = fmaf(a[i], bb[j], acc[i][j]);
    }

    const float inv = 0.03125f;  // 1/sqrt(E) = 1/32
    float* Sp = g_S + (size_t)bh*Tc*Tc;
    #pragma unroll
    for (int i = 0; i < 4; i++) {
        int t = ti*64 + ty*4 + i;
        #pragma unroll
        for (int j = 0; j < 4; j++) {
            int s = tj*64 + tx*4 + j;
            Sp[(size_t)t*Tc + s] = (s <= t) ? acc[i][j]*inv : -1e30f;
        }
    }
}

// ---------------------------------------------------------------------------
// Kernel 3: per-KEY column stats (softmax over the query axis).
// For column s: m_s = max_{t>=s} S[t][s], Z_s = sum exp(S - m_s).
// ---------------------------------------------------------------------------
__global__ void colstats_kernel() {
    const int j = blockIdx.x, bh = blockIdx.y;
    const int tid = threadIdx.x;
    const int tx = tid & 63, ty = tid >> 6;
    const int s = j*64 + tx;
    const float* Sp = g_S + (size_t)bh*Tc*Tc;

    float m = -INFINITY, z = 0.f;
    for (int t = j*64 + ty; t < Tc; t += 4) {
        float v = Sp[(size_t)t*Tc + s];
        if (v > m) { z = z*__expf(m - v) + 1.f; m = v; }
        else       { z += __expf(v - m); }
    }
    __shared__ float sm[4][64], sz[4][64];
    sm[ty][tx] = m; sz[ty][tx] = z;
    __syncthreads();
    if (tid < 64) {
        float M = sm[0][tid];
        #pragma unroll
        for (int k = 1; k < 4; k++) M = fmaxf(M, sm[k][tid]);
        float Z = 0.f;
        #pragma unroll
        for (int k = 0; k < 4; k++) Z += sz[k][tid]*__expf(sm[k][tid] - M);
        g_m [bh*Tc + j*64 + tid] = M;
        g_iz[bh*Tc + j*64 + tid] = 1.f / Z;
    }
}

// ---------------------------------------------------------------------------
// Kernel 4: O[t][d] = sum_{s<=t} exp(S[t][s]-m_s)*invZ_s * V[s][d]
// ---------------------------------------------------------------------------
__global__ void av_kernel() {
    const int ti = gridDim.x - 1 - blockIdx.x;   // longest blocks first
    const int bh = blockIdx.y;
    __shared__ float Ps[64][65];
    __shared__ float Vs[64][64];
    __shared__ float cm[64], ciz[64];
    const int tid = threadIdx.x;
    const int tx = tid & 15, ty = tid >> 4;

    float acc[4][4] = {};
    const float* Sp = g_S + ((size_t)bh*Tc + ti*64) * Tc;

    for (int j = 0; j <= ti; j++) {
        if (tid < 64) {
            cm [tid] = g_m [bh*Tc + j*64 + tid];
            ciz[tid] = g_iz[bh*Tc + j*64 + tid];
        }
        __syncthreads();
        #pragma unroll
        for (int it = 0; it < 16; it++) {
            int idx = it*256 + tid;
            int r = idx >> 6, c = idx & 63;
            float v = Sp[(size_t)r*Tc + j*64 + c];
            Ps[r][c] = __expf(v - cm[c]) * ciz[c];
            Vs[r][c] = g_V[((size_t)bh*Tc + j*64 + r)*HSc + c];
        }
        __syncthreads();
        #pragma unroll
        for (int kk = 0; kk < 64; kk++) {
            float a[4], bb[4];
            #pragma unroll
            for (int i = 0; i < 4; i++) a[i]  = Ps[ty*4+i][kk];
            #pragma unroll
            for (int j2 = 0; j2 < 4; j2++) bb[j2] = Vs[kk][tx*4+j2];
            #pragma unroll
            for (int i = 0; i < 4; i++)
                #pragma unroll
                for (int j2 = 0; j2 < 4; j2++)
                    acc[i][j2] = fmaf(a[i], bb[j2], acc[i][j2]);
        }
        __syncthreads();
    }

    #pragma unroll
    for (int i = 0; i < 4; i++) {
        size_t o = ((size_t)bh*Tc + ti*64 + ty*4 + i) * HSc;
        #pragma unroll
        for (int j2 = 0; j2 < 4; j2++)
            g_O[o + tx*4 + j2] = acc[i][j2];
    }
}

// ---------------------------------------------------------------------------
// Kernel 5: output projection.  Y[bt][n] = concat[bt][:] @ Wo[:, n] + bo[n]
// concat[b,t,h*64+d] = g_O[((b*H+h)*T + t)*64 + d]
// ---------------------------------------------------------------------------
__global__ void outproj_kernel(const float* __restrict__ Wo,
                               const float* __restrict__ bo,
                               float* __restrict__ out) {
    __shared__ float As[64][33];
    __shared__ float Bs[32][64];
    const int mi = blockIdx.x, ni = blockIdx.y;
    const int tid = threadIdx.x;
    const int tx = tid & 15, ty = tid >> 4;
    const int row0 = mi*64;

    float acc[4][4] = {};

    for (int k0 = 0; k0 < Ec; k0 += 32) {
        const int h = k0 >> 6;
        const int dbase = k0 & 63;
        #pragma unroll
        for (int it = 0; it < 8; it++) {
            int idx = it*256 + tid;
            int r = idx >> 5, c = idx & 31;
            int bt = row0 + r;
            int b = bt >> 11, t = bt & 2047;
            As[r][c] = g_O[(((size_t)b*Hc + h)*Tc + t)*HSc + dbase + c];
        }
        #pragma unroll
        for (int it = 0; it < 8; it++) {
            int idx = it*256 + tid;
            int r = idx >> 6, c = idx & 63;
            Bs[r][c] = Wo[(size_t)(k0 + r)*Ec + ni*64 + c];
        }
        __syncthreads();
        #pragma unroll
        for (int kk = 0; kk < 32; kk++) {
            float a[4], bb[4];
            #pragma unroll
            for (int i = 0; i < 4; i++) a[i]  = As[ty*4+i][kk];
            #pragma unroll
            for (int j = 0; j < 4; j++) bb[j] = Bs[kk][tx*4+j];
            #pragma unroll
            for (int i = 0; i < 4; i++)
                #pragma unroll
                for (int j = 0; j < 4; j++)
                    acc[i][j] = fmaf(a[i], bb[j], acc[i][j]);
        }
        __syncthreads();
    }

    #pragma unroll
    for (int i = 0; i < 4; i++) {
        int bt = row0 + ty*4 + i;
        #pragma unroll
        for (int j = 0; j < 4; j++) {
            int n = ni*64 + tx*4 + j;
            out[(size_t)bt*Ec + n] = acc[i][j] + bo[n];
        }
    }
}

// ---------------------------------------------------------------------------
extern "C" void kernel_launch(void* const* d_in, const int* in_sizes, int n_in,
                              void* d_out, int out_size) {
    const float* x  = (const float*)d_in[0];
    const float* Wq = (const float*)d_in[1];
    const float* Wk = (const float*)d_in[2];
    const float* Wv = (const float*)d_in[3];
    const float* Wo = (const float*)d_in[4];
    const float* bo = (const float*)d_in[5];
    float* out = (float*)d_out;

    qkv_kernel    <<<dim3(Tc/64, BHc),      256>>>(x, Wq, Wk, Wv);
    scores_kernel <<<dim3(Tc/64, Tc/64, BHc), 256>>>();
    colstats_kernel<<<dim3(Tc/64, BHc),     256>>>();
    av_kernel     <<<dim3(Tc/64, BHc),      256>>>();
    outproj_kernel<<<dim3((Bc*Tc)/64, Ec/64), 256>>>(Wo, bo, out);
}

// round 10
// speedup vs baseline: 2.0315x; 2.0315x over previous
#include <cuda_runtime.h>
#include <cuda_bf16.h>
#include <math.h>
#include <stdint.h>

// Problem constants
#define Bc 4
#define Tc 2048
#define Ec 1024
#define Hc 16
#define HSc 64
#define BHc (Bc*Hc)

// ---------------------------------------------------------------------------
// Scratch (static device arrays; allocation APIs are forbidden)
// ---------------------------------------------------------------------------
__device__ float g_S[(size_t)BHc*Tc*Tc];    // 1 GiB (lower-tri tiles only)
__device__ float g_m[BHc*Tc];
__device__ float g_iz[BHc*Tc];

// bf16 hi/lo split operands for tensor-core GEMMs
__device__ __nv_bfloat16 g_Xhi[(size_t)Bc*Tc*Ec];
__device__ __nv_bfloat16 g_Xlo[(size_t)Bc*Tc*Ec];
__device__ __nv_bfloat16 g_Wthi[(size_t)3*Hc*HSc*Ec];   // W^T: [g][h][d][e]
__device__ __nv_bfloat16 g_Wtlo[(size_t)3*Hc*HSc*Ec];
__device__ __nv_bfloat16 g_Qhi[(size_t)BHc*Tc*HSc];     // Q bf16 hi/lo [bh][t][d]
__device__ __nv_bfloat16 g_Qlo[(size_t)BHc*Tc*HSc];
__device__ __nv_bfloat16 g_Khi[(size_t)BHc*Tc*HSc];     // K bf16 hi/lo [bh][s][d]
__device__ __nv_bfloat16 g_Klo[(size_t)BHc*Tc*HSc];
__device__ __nv_bfloat16 g_Vhi[(size_t)BHc*Tc*HSc];     // V bf16 hi/lo [bh][s][d]
__device__ __nv_bfloat16 g_Vlo[(size_t)BHc*Tc*HSc];
__device__ __nv_bfloat16 g_Ohi[(size_t)Bc*Tc*Ec];       // head-concat [bt][e]
__device__ __nv_bfloat16 g_Olo[(size_t)Bc*Tc*Ec];
__device__ __nv_bfloat16 g_WoThi[(size_t)Ec*Ec];        // Wo^T: [n][k]
__device__ __nv_bfloat16 g_WoTlo[(size_t)Ec*Ec];

// ---------------------------------------------------------------------------
// mma.sync helpers (sm_80+ path; compiles on base sm_103 target)
// ---------------------------------------------------------------------------
__device__ __forceinline__ uint32_t smem_u32(const void* p) {
    uint32_t a;
    asm("{ .reg .u64 t; cvta.to.shared.u64 t, %1; cvt.u32.u64 %0, t; }" : "=r"(a) : "l"(p));
    return a;
}
__device__ __forceinline__ void ldsm4(uint32_t* r, uint32_t addr) {
    asm volatile("ldmatrix.sync.aligned.m8n8.x4.shared.b16 {%0,%1,%2,%3}, [%4];"
        : "=r"(r[0]), "=r"(r[1]), "=r"(r[2]), "=r"(r[3]) : "r"(addr));
}
__device__ __forceinline__ void ldsm4t(uint32_t* r, uint32_t addr) {
    asm volatile("ldmatrix.sync.aligned.m8n8.x4.trans.shared.b16 {%0,%1,%2,%3}, [%4];"
        : "=r"(r[0]), "=r"(r[1]), "=r"(r[2]), "=r"(r[3]) : "r"(addr));
}
__device__ __forceinline__ void mma16816(float* d, const uint32_t* a, uint32_t b0, uint32_t b1) {
    asm volatile("mma.sync.aligned.m16n8k16.row.col.f32.bf16.bf16.f32 "
        "{%0,%1,%2,%3}, {%4,%5,%6,%7}, {%8,%9}, {%0,%1,%2,%3};"
        : "+f"(d[0]), "+f"(d[1]), "+f"(d[2]), "+f"(d[3])
        : "r"(a[0]), "r"(a[1]), "r"(a[2]), "r"(a[3]), "r"(b0), "r"(b1));
}
__device__ __forceinline__ void split_bf16(float v, __nv_bfloat16& hi, __nv_bfloat16& lo) {
    hi = __float2bfloat16(v);
    lo = __float2bfloat16(v - __bfloat162float(hi));
}

// ---------------------------------------------------------------------------
// Convert kernels
// ---------------------------------------------------------------------------
__global__ void convx_kernel(const float* __restrict__ x) {
    size_t i = (size_t)blockIdx.x * blockDim.x + threadIdx.x;   // one float4 each
    float4 v = ((const float4*)x)[i];
    __nv_bfloat16 h0,l0,h1,l1,h2,l2,h3,l3;
    split_bf16(v.x,h0,l0); split_bf16(v.y,h1,l1); split_bf16(v.z,h2,l2); split_bf16(v.w,h3,l3);
    ((__nv_bfloat162*)g_Xhi)[2*i]   = __nv_bfloat162(h0,h1);
    ((__nv_bfloat162*)g_Xhi)[2*i+1] = __nv_bfloat162(h2,h3);
    ((__nv_bfloat162*)g_Xlo)[2*i]   = __nv_bfloat162(l0,l1);
    ((__nv_bfloat162*)g_Xlo)[2*i+1] = __nv_bfloat162(l2,l3);
}

// W[h][e][d] (fp32) -> Wt[g][h][d][e] (bf16 hi/lo)
__global__ void convw_kernel(const float* __restrict__ Wq,
                             const float* __restrict__ Wk,
                             const float* __restrict__ Wv) {
    const int h = blockIdx.x, g = blockIdx.y;
    const float* W = (g == 0 ? Wq : g == 1 ? Wk : Wv) + (size_t)h*Ec*HSc;
    const int tid = threadIdx.x;
    for (int it = 0; it < (Ec*HSc)/256; it++) {
        int idx = it*256 + tid;
        int d = idx >> 10, e = idx & 1023;
        float v = W[(size_t)e*HSc + d];
        __nv_bfloat16 hi, lo; split_bf16(v, hi, lo);
        size_t o = ((size_t)(g*Hc + h)*HSc + d)*Ec + e;
        g_Wthi[o] = hi; g_Wtlo[o] = lo;
    }
}

// Wo[k][n] -> WoT[n][k] bf16 hi/lo
__global__ void convwo_kernel(const float* __restrict__ Wo) {
    int idx = blockIdx.x*256 + threadIdx.x;
    int n = idx >> 10, k = idx & 1023;
    float v = Wo[(size_t)k*Ec + n];
    __nv_bfloat16 hi, lo; split_bf16(v, hi, lo);
    g_WoThi[(size_t)n*Ec + k] = hi;
    g_WoTlo[(size_t)n*Ec + k] = lo;
}

// ---------------------------------------------------------------------------
// mma.sync QKV: block = 64 t-rows x 192 out-cols (Q|K|V), K=1024.
// 8 warps as 2(M) x 4(N): warp tile 32x48.  3-term bf16 hi/lo split.
// Epilogue: Q,K,V all written as bf16 hi/lo.
// ---------------------------------------------------------------------------
#define QK_AH 0
#define QK_AL (64*72)
#define QK_BH (2*64*72)
#define QK_BL (2*64*72 + 192*72)
#define QK_SMEM ((2*64*72 + 2*192*72)*2)   // 73728 bytes

__global__ __launch_bounds__(256) void qkv_mma_kernel() {
    extern __shared__ __nv_bfloat16 sm[];
    const int ti = blockIdx.x, bh = blockIdx.y;
    const int b = bh >> 4, h = bh & 15;
    const int tid = threadIdx.x, wid = tid >> 5, lid = tid & 31;
    const int m0 = (wid & 1)*32, n0 = (wid >> 1)*48;
    const uint32_t sb = smem_u32(sm);

    float acc[2][6][4] = {};

    for (int chunk = 0; chunk < 16; chunk++) {
        const int k0 = chunk*64;
        #pragma unroll
        for (int it = 0; it < 2; it++) {          // A: 64 rows x 64 bf16, hi+lo
            int idx = it*256 + tid;
            int r = idx >> 3, c = idx & 7;
            size_t src = ((size_t)(b*Tc + ti*64 + r))*Ec + k0 + c*8;
            *(uint4*)(sm + QK_AH + r*72 + c*8) = *(const uint4*)(g_Xhi + src);
            *(uint4*)(sm + QK_AL + r*72 + c*8) = *(const uint4*)(g_Xlo + src);
        }
        #pragma unroll
        for (int it = 0; it < 6; it++) {          // B: 192 rows x 64 bf16, hi+lo
            int idx = it*256 + tid;
            int r = idx >> 3, c = idx & 7;
            int g = r >> 6, d = r & 63;
            size_t src = ((size_t)((g*Hc + h)*HSc + d))*Ec + k0 + c*8;
            *(uint4*)(sm + QK_BH + r*72 + c*8) = *(const uint4*)(g_Wthi + src);
            *(uint4*)(sm + QK_BL + r*72 + c*8) = *(const uint4*)(g_Wtlo + src);
        }
        __syncthreads();

        #pragma unroll
        for (int ks = 0; ks < 4; ks++) {
            const int kk = ks*16;
            uint32_t aH[2][4], aL[2][4], bH[3][4], bL[3][4];
            const int arow = lid & 15;
            const int akoff = ((lid >> 4) & 1)*8 + kk;
            #pragma unroll
            for (int mi = 0; mi < 2; mi++) {
                uint32_t off = (uint32_t)((m0 + mi*16 + arow)*72 + akoff)*2;
                ldsm4(aH[mi], sb + QK_AH*2 + off);
                ldsm4(aL[mi], sb + QK_AL*2 + off);
            }
            const int brow = (lid & 7) + ((lid >> 4) & 1)*8;
            const int bkoff = ((lid >> 3) & 1)*8 + kk;
            #pragma unroll
            for (int ng = 0; ng < 3; ng++) {
                uint32_t off = (uint32_t)((n0 + ng*16 + brow)*72 + bkoff)*2;
                ldsm4(bH[ng], sb + QK_BH*2 + off);
                ldsm4(bL[ng], sb + QK_BL*2 + off);
            }
            #pragma unroll
            for (int mi = 0; mi < 2; mi++)
                #pragma unroll
                for (int ng = 0; ng < 3; ng++) {
                    mma16816(acc[mi][ng*2  ], aH[mi], bH[ng][0], bH[ng][1]);
                    mma16816(acc[mi][ng*2+1], aH[mi], bH[ng][2], bH[ng][3]);
                    mma16816(acc[mi][ng*2  ], aH[mi], bL[ng][0], bL[ng][1]);
                    mma16816(acc[mi][ng*2+1], aH[mi], bL[ng][2], bL[ng][3]);
                    mma16816(acc[mi][ng*2  ], aL[mi], bH[ng][0], bH[ng][1]);
                    mma16816(acc[mi][ng*2+1], aL[mi], bH[ng][2], bH[ng][3]);
                }
        }
        __syncthreads();
    }

    // Epilogue: Q,K,V -> bf16 hi/lo.
    const int gl = lid >> 2, il = lid & 3;
    #pragma unroll
    for (int mi = 0; mi < 2; mi++) {
        #pragma unroll
        for (int j = 0; j < 6; j++) {
            int col = n0 + j*8 + il*2;
            int g = col >> 6, d = col & 63;
            size_t t0 = (size_t)bh*Tc + ti*64 + m0 + mi*16 + gl;
            __nv_bfloat16* dh = (g == 0) ? g_Qhi : (g == 1) ? g_Khi : g_Vhi;
            __nv_bfloat16* dl = (g == 0) ? g_Qlo : (g == 1) ? g_Klo : g_Vlo;
            __nv_bfloat16 h0,l0,h1,l1;
            split_bf16(acc[mi][j][0], h0, l0);
            split_bf16(acc[mi][j][1], h1, l1);
            *(__nv_bfloat162*)&dh[t0*HSc + d] = __nv_bfloat162(h0, h1);
            *(__nv_bfloat162*)&dl[t0*HSc + d] = __nv_bfloat162(l0, l1);
            split_bf16(acc[mi][j][2], h0, l0);
            split_bf16(acc[mi][j][3], h1, l1);
            *(__nv_bfloat162*)&dh[(t0+8)*HSc + d] = __nv_bfloat162(h0, h1);
            *(__nv_bfloat162*)&dl[(t0+8)*HSc + d] = __nv_bfloat162(l0, l1);
        }
    }
}

// ---------------------------------------------------------------------------
// mma.sync scores: block = 64x64 tile of S, lower-tri tiles only, K=64.
// S[t][s] = (Q[t]·K[s])/32, masked s>t -> -1e30.
// ---------------------------------------------------------------------------
__global__ __launch_bounds__(256) void scores_mma_kernel() {
    const int tj = blockIdx.x, ti = blockIdx.y, bh = blockIdx.z;
    if (tj > ti) return;
    __shared__ __nv_bfloat16 Qh[64][72], Ql[64][72], Kh[64][72], Kl[64][72];
    const int tid = threadIdx.x, wid = tid >> 5, lid = tid & 31;
    const int m0 = (wid & 1)*32, n0 = (wid >> 1)*16;

    #pragma unroll
    for (int it = 0; it < 2; it++) {
        int idx = it*256 + tid;
        int r = idx >> 3, c = idx & 7;
        size_t srcQ = ((size_t)bh*Tc + ti*64 + r)*HSc + c*8;
        size_t srcK = ((size_t)bh*Tc + tj*64 + r)*HSc + c*8;
        *(uint4*)&Qh[r][c*8] = *(const uint4*)(g_Qhi + srcQ);
        *(uint4*)&Ql[r][c*8] = *(const uint4*)(g_Qlo + srcQ);
        *(uint4*)&Kh[r][c*8] = *(const uint4*)(g_Khi + srcK);
        *(uint4*)&Kl[r][c*8] = *(const uint4*)(g_Klo + srcK);
    }
    __syncthreads();

    float acc[2][2][4] = {};
    #pragma unroll
    for (int ks = 0; ks < 4; ks++) {
        const int kk = ks*16;
        uint32_t aH[2][4], aL[2][4], bHf[4], bLf[4];
        const int arow = lid & 15;
        const int akoff = ((lid >> 4) & 1)*8 + kk;
        #pragma unroll
        for (int mi = 0; mi < 2; mi++) {
            ldsm4(aH[mi], smem_u32(&Qh[m0 + mi*16 + arow][akoff]));
            ldsm4(aL[mi], smem_u32(&Ql[m0 + mi*16 + arow][akoff]));
        }
        const int brow = (lid & 7) + ((lid >> 4) & 1)*8;
        const int bkoff = ((lid >> 3) & 1)*8 + kk;
        ldsm4(bHf, smem_u32(&Kh[n0 + brow][bkoff]));
        ldsm4(bLf, smem_u32(&Kl[n0 + brow][bkoff]));
        #pragma unroll
        for (int mi = 0; mi < 2; mi++) {
            mma16816(acc[mi][0], aH[mi], bHf[0], bHf[1]);
            mma16816(acc[mi][1], aH[mi], bHf[2], bHf[3]);
            mma16816(acc[mi][0], aH[mi], bLf[0], bLf[1]);
            mma16816(acc[mi][1], aH[mi], bLf[2], bLf[3]);
            mma16816(acc[mi][0], aL[mi], bHf[0], bHf[1]);
            mma16816(acc[mi][1], aL[mi], bHf[2], bHf[3]);
        }
    }

    const float inv = 0.03125f;   // 1/sqrt(E)
    float* Sp = g_S + (size_t)bh*Tc*Tc;
    const int gl = lid >> 2, il = lid & 3;
    #pragma unroll
    for (int mi = 0; mi < 2; mi++) {
        #pragma unroll
        for (int j = 0; j < 2; j++) {
            int s = tj*64 + n0 + j*8 + il*2;
            int t = ti*64 + m0 + mi*16 + gl;
            float v0 = (s   <= t) ? acc[mi][j][0]*inv : -1e30f;
            float v1 = (s+1 <= t) ? acc[mi][j][1]*inv : -1e30f;
            *(float2*)&Sp[(size_t)t*Tc + s] = make_float2(v0, v1);
            int t2 = t + 8;
            float v2 = (s   <= t2) ? acc[mi][j][2]*inv : -1e30f;
            float v3 = (s+1 <= t2) ? acc[mi][j][3]*inv : -1e30f;
            *(float2*)&Sp[(size_t)t2*Tc + s] = make_float2(v2, v3);
        }
    }
}

// ---------------------------------------------------------------------------
// Kernel 3: per-KEY column stats (softmax over the query axis).
// ---------------------------------------------------------------------------
__global__ void colstats_kernel() {
    const int j = blockIdx.x, bh = blockIdx.y;
    const int tid = threadIdx.x;
    const int tx = tid & 63, ty = tid >> 6;
    const int s = j*64 + tx;
    const float* Sp = g_S + (size_t)bh*Tc*Tc;

    float m = -INFINITY, z = 0.f;
    for (int t = j*64 + ty; t < Tc; t += 4) {
        float v = Sp[(size_t)t*Tc + s];
        if (v > m) { z = z*__expf(m - v) + 1.f; m = v; }
        else       { z += __expf(v - m); }
    }
    __shared__ float sm[4][64], sz[4][64];
    sm[ty][tx] = m; sz[ty][tx] = z;
    __syncthreads();
    if (tid < 64) {
        float M = sm[0][tid];
        #pragma unroll
        for (int k = 1; k < 4; k++) M = fmaxf(M, sm[k][tid]);
        float Z = 0.f;
        #pragma unroll
        for (int k = 0; k < 4; k++) Z += sz[k][tid]*__expf(sm[k][tid] - M);
        g_m [bh*Tc + j*64 + tid] = M;
        g_iz[bh*Tc + j*64 + tid] = 1.f / Z;
    }
}

// ---------------------------------------------------------------------------
// mma.sync A·V: block = 64 t-rows x 64 d-cols per bh.  K-loop over s-tiles.
// A = P[t][s] = exp(S-m_s)*iz_s (fp32 -> hi/lo split in smem).
// B = V[s][d] bf16 hi/lo, loaded as row-major [k][n] and fed via ldmatrix.trans.
// Epilogue writes head-concat bf16 hi/lo for outproj.
// ---------------------------------------------------------------------------
__global__ __launch_bounds__(256) void av_mma_kernel() {
    const int ti = gridDim.x - 1 - blockIdx.x;   // longest blocks first
    const int bh = blockIdx.y;
    const int b = bh >> 4, h = bh & 15;
    __shared__ __nv_bfloat16 Ph[64][72], Pl[64][72], Vh[64][72], Vl[64][72];
    __shared__ float cm[64], ciz[64];
    const int tid = threadIdx.x, wid = tid >> 5, lid = tid & 31;
    const int m0 = (wid & 1)*32, n0 = (wid >> 1)*16;

    float acc[2][2][4] = {};
    const float* Sp = g_S + ((size_t)bh*Tc + ti*64) * Tc;

    for (int j = 0; j <= ti; j++) {
        __syncthreads();   // previous iteration's ldsm reads complete
        if (tid < 64) {
            cm [tid] = g_m [bh*Tc + j*64 + tid];
            ciz[tid] = g_iz[bh*Tc + j*64 + tid];
        }
        __syncthreads();   // cm/ciz visible

        #pragma unroll
        for (int it = 0; it < 2; it++) {
            int idx = it*256 + tid;
            int r = idx >> 3, c = (idx & 7)*8;
            // P = exp(S - m_s) * iz_s  (masked entries: exp(-1e30-m) = 0)
            const float* srow = &Sp[(size_t)r*Tc + j*64 + c];
            float4 v0 = *(const float4*)(srow);
            float4 v1 = *(const float4*)(srow + 4);
            float p[8];
            p[0] = __expf(v0.x - cm[c  ]) * ciz[c  ];
            p[1] = __expf(v0.y - cm[c+1]) * ciz[c+1];
            p[2] = __expf(v0.z - cm[c+2]) * ciz[c+2];
            p[3] = __expf(v0.w - cm[c+3]) * ciz[c+3];
            p[4] = __expf(v1.x - cm[c+4]) * ciz[c+4];
            p[5] = __expf(v1.y - cm[c+5]) * ciz[c+5];
            p[6] = __expf(v1.z - cm[c+6]) * ciz[c+6];
            p[7] = __expf(v1.w - cm[c+7]) * ciz[c+7];
            #pragma unroll
            for (int q = 0; q < 8; q += 2) {
                __nv_bfloat16 h0,l0,h1,l1;
                split_bf16(p[q],   h0, l0);
                split_bf16(p[q+1], h1, l1);
                *(__nv_bfloat162*)&Ph[r][c+q] = __nv_bfloat162(h0, h1);
                *(__nv_bfloat162*)&Pl[r][c+q] = __nv_bfloat162(l0, l1);
            }
            // V tile rows (s = j*64 + r)
            size_t srcV = ((size_t)bh*Tc + j*64 + r)*HSc + c;
            *(uint4*)&Vh[r][c] = *(const uint4*)(g_Vhi + srcV);
            *(uint4*)&Vl[r][c] = *(const uint4*)(g_Vlo + srcV);
        }
        __syncthreads();   // smem tiles ready

        #pragma unroll
        for (int ks = 0; ks < 4; ks++) {
            const int kk = ks*16;
            uint32_t aH[2][4], aL[2][4], bHf[4], bLf[4];
            const int arow = lid & 15;
            const int akoff = ((lid >> 4) & 1)*8 + kk;
            #pragma unroll
            for (int mi = 0; mi < 2; mi++) {
                ldsm4(aH[mi], smem_u32(&Ph[m0 + mi*16 + arow][akoff]));
                ldsm4(aL[mi], smem_u32(&Pl[m0 + mi*16 + arow][akoff]));
            }
            // trans B: row = k, col = n.  mat0=(k0-7,n0-7) mat1=(k8-15,n0-7)
            //                              mat2=(k0-7,n8-15) mat3=(k8-15,n8-15)
            const int brow = kk + (lid & 7) + ((lid >> 3) & 1)*8;
            const int bcol = n0 + ((lid >> 4) & 1)*8;
            ldsm4t(bHf, smem_u32(&Vh[brow][bcol]));
            ldsm4t(bLf, smem_u32(&Vl[brow][bcol]));
            #pragma unroll
            for (int mi = 0; mi < 2; mi++) {
                mma16816(acc[mi][0], aH[mi], bHf[0], bHf[1]);
                mma16816(acc[mi][1], aH[mi], bHf[2], bHf[3]);
                mma16816(acc[mi][0], aH[mi], bLf[0], bLf[1]);
                mma16816(acc[mi][1], aH[mi], bLf[2], bLf[3]);
                mma16816(acc[mi][0], aL[mi], bHf[0], bHf[1]);
                mma16816(acc[mi][1], aL[mi], bHf[2], bHf[3]);
            }
        }
    }

    // Epilogue: head-concat bf16 hi/lo.
    const int gl = lid >> 2, il = lid & 3;
    #pragma unroll
    for (int mi = 0; mi < 2; mi++) {
        #pragma unroll
        for (int jj = 0; jj < 2; jj++) {
            int d = n0 + jj*8 + il*2;
            size_t row = (size_t)b*Tc + ti*64 + m0 + mi*16 + gl;
            __nv_bfloat16 h0,l0,h1,l1;
            split_bf16(acc[mi][jj][0], h0, l0);
            split_bf16(acc[mi][jj][1], h1, l1);
            *(__nv_bfloat162*)&g_Ohi[row*Ec + h*HSc + d] = __nv_bfloat162(h0, h1);
            *(__nv_bfloat162*)&g_Olo[row*Ec + h*HSc + d] = __nv_bfloat162(l0, l1);
            split_bf16(acc[mi][jj][2], h0, l0);
            split_bf16(acc[mi][jj][3], h1, l1);
            *(__nv_bfloat162*)&g_Ohi[(row+8)*Ec + h*HSc + d] = __nv_bfloat162(h0, h1);
            *(__nv_bfloat162*)&g_Olo[(row+8)*Ec + h*HSc + d] = __nv_bfloat162(l0, l1);
        }
    }
}

// ---------------------------------------------------------------------------
// mma.sync output projection: block = 64 bt-rows x 64 n-cols, K=1024.
// ---------------------------------------------------------------------------
__global__ __launch_bounds__(256) void outproj_mma_kernel(const float* __restrict__ bo,
                                                          float* __restrict__ out) {
    __shared__ __nv_bfloat16 Ah[64][72], Al[64][72], Bh[64][72], Bl[64][72];
    const int row0 = blockIdx.x*64, ni = blockIdx.y;
    const int tid = threadIdx.x, wid = tid >> 5, lid = tid & 31;
    const int m0 = (wid & 1)*32, n0 = (wid >> 1)*16;

    float acc[2][2][4] = {};

    for (int chunk = 0; chunk < 16; chunk++) {
        const int k0 = chunk*64;
        #pragma unroll
        for (int it = 0; it < 2; it++) {
            int idx = it*256 + tid;
            int r = idx >> 3, c = idx & 7;
            size_t srcA = ((size_t)(row0 + r))*Ec + k0 + c*8;
            size_t srcB = ((size_t)(ni*64 + r))*Ec + k0 + c*8;
            *(uint4*)&Ah[r][c*8] = *(const uint4*)(g_Ohi + srcA);
            *(uint4*)&Al[r][c*8] = *(const uint4*)(g_Olo + srcA);
            *(uint4*)&Bh[r][c*8] = *(const uint4*)(g_WoThi + srcB);
            *(uint4*)&Bl[r][c*8] = *(const uint4*)(g_WoTlo + srcB);
        }
        __syncthreads();

        #pragma unroll
        for (int ks = 0; ks < 4; ks++) {
            const int kk = ks*16;
            uint32_t aH[2][4], aL[2][4], bHf[4], bLf[4];
            const int arow = lid & 15;
            const int akoff = ((lid >> 4) & 1)*8 + kk;
            #pragma unroll
            for (int mi = 0; mi < 2; mi++) {
                ldsm4(aH[mi], smem_u32(&Ah[m0 + mi*16 + arow][akoff]));
                ldsm4(aL[mi], smem_u32(&Al[m0 + mi*16 + arow][akoff]));
            }
            const int brow = (lid & 7) + ((lid >> 4) & 1)*8;
            const int bkoff = ((lid >> 3) & 1)*8 + kk;
            ldsm4(bHf, smem_u32(&Bh[n0 + brow][bkoff]));
            ldsm4(bLf, smem_u32(&Bl[n0 + brow][bkoff]));
            #pragma unroll
            for (int mi = 0; mi < 2; mi++) {
                mma16816(acc[mi][0], aH[mi], bHf[0], bHf[1]);
                mma16816(acc[mi][1], aH[mi], bHf[2], bHf[3]);
                mma16816(acc[mi][0], aH[mi], bLf[0], bLf[1]);
                mma16816(acc[mi][1], aH[mi], bLf[2], bLf[3]);
                mma16816(acc[mi][0], aL[mi], bHf[0], bHf[1]);
                mma16816(acc[mi][1], aL[mi], bHf[2], bHf[3]);
            }
        }
        __syncthreads();
    }

    const int gl = lid >> 2, il = lid & 3;
    #pragma unroll
    for (int mi = 0; mi < 2; mi++) {
        #pragma unroll
        for (int j = 0; j < 2; j++) {
            int n = ni*64 + n0 + j*8 + il*2;
            size_t r = (size_t)row0 + m0 + mi*16 + gl;
            out[r*Ec + n]       = acc[mi][j][0] + bo[n];
            out[r*Ec + n + 1]   = acc[mi][j][1] + bo[n+1];
            out[(r+8)*Ec + n]   = acc[mi][j][2] + bo[n];
            out[(r+8)*Ec + n+1] = acc[mi][j][3] + bo[n+1];
        }
    }
}

// ---------------------------------------------------------------------------
extern "C" void kernel_launch(void* const* d_in, const int* in_sizes, int n_in,
                              void* d_out, int out_size) {
    const float* x  = (const float*)d_in[0];
    const float* Wq = (const float*)d_in[1];
    const float* Wk = (const float*)d_in[2];
    const float* Wv = (const float*)d_in[3];
    const float* Wo = (const float*)d_in[4];
    const float* bo = (const float*)d_in[5];
    float* out = (float*)d_out;

    cudaFuncSetAttribute(qkv_mma_kernel, cudaFuncAttributeMaxDynamicSharedMemorySize, QK_SMEM);

    convx_kernel <<<(Bc*Tc*Ec)/(256*4), 256>>>(x);
    convw_kernel <<<dim3(Hc, 3), 256>>>(Wq, Wk, Wv);
    convwo_kernel<<<(Ec*Ec)/256, 256>>>(Wo);

    qkv_mma_kernel<<<dim3(Tc/64, BHc), 256, QK_SMEM>>>();

    scores_mma_kernel<<<dim3(Tc/64, Tc/64, BHc), 256>>>();
    colstats_kernel  <<<dim3(Tc/64, BHc), 256>>>();
    av_mma_kernel    <<<dim3(Tc/64, BHc), 256>>>();

    outproj_mma_kernel<<<dim3((Bc*Tc)/64, Ec/64), 256>>>(bo, out);
}